// round 14
// baseline (speedup 1.0000x reference)
#include <cuda_runtime.h>
#include <cuda_fp16.h>
#include <cstdint>

#define BB 4
#define SS 2048
#define DD 1024
#define PP 1024

// ---------------- scratch (device globals; no allocation allowed) ----------
__device__ __half g_qkh[(size_t)BB * SS * 2048];        // rows: [q(1024) | k(1024)]
__device__ __half g_vt [(size_t)BB * PP * SS];          // per-batch (P, S)
__device__ float  g_s  [(size_t)BB * SS * SS];          // scores fp32 (pre-scaled)
__device__ __half g_ph [(size_t)BB * SS * SS];          // probs half
__device__ __half g_xh [(size_t)BB * SS * DD];          // x in half
__device__ __half g_wt [3][(size_t)PP * DD];            // Wq^T,Wk^T,Wv^T half (contig)

// ---------------- helpers ---------------------------------------------------
__device__ __forceinline__ uint32_t smem_u32(const void* p) {
    uint32_t a;
    asm("{ .reg .u64 t; cvta.to.shared.u64 t, %1; cvt.u32.u64 %0, t; }"
        : "=r"(a) : "l"(p));
    return a;
}

#define CP_ASYNC16(dst_u32, src_ptr) \
    asm volatile("cp.async.cg.shared.global [%0], [%1], 16;" \
                 :: "r"(dst_u32), "l"(src_ptr) : "memory")
#define CP_COMMIT() asm volatile("cp.async.commit_group;" ::: "memory")
#define CP_WAIT(n)  asm volatile("cp.async.wait_group %0;" :: "n"(n) : "memory")

#define LDSM_X4(r0, r1, r2, r3, addr) \
    asm volatile("ldmatrix.sync.aligned.m8n8.x4.shared.b16 {%0,%1,%2,%3}, [%4];" \
                 : "=r"(r0), "=r"(r1), "=r"(r2), "=r"(r3) : "r"(addr))

__device__ __forceinline__ void mma_f16(float* c, const uint32_t* a, const uint32_t* b) {
    asm volatile(
        "mma.sync.aligned.m16n8k16.row.col.f32.f16.f16.f32 "
        "{%0,%1,%2,%3}, {%4,%5,%6,%7}, {%8,%9}, {%0,%1,%2,%3};"
        : "+f"(c[0]), "+f"(c[1]), "+f"(c[2]), "+f"(c[3])
        : "r"(a[0]), "r"(a[1]), "r"(a[2]), "r"(a[3]), "r"(b[0]), "r"(b[1]));
}

// ---------------- conversion kernels ----------------------------------------
__global__ __launch_bounds__(256) void f2h(
    const float* __restrict__ in, __half* __restrict__ out, int n4)
{
    int i = blockIdx.x * 256 + threadIdx.x;
    if (i >= n4) return;
    float4 v = reinterpret_cast<const float4*>(in)[i];
    __half2 lo = __floats2half2_rn(v.x, v.y);
    __half2 hi = __floats2half2_rn(v.z, v.w);
    reinterpret_cast<uint2*>(out)[i] =
        make_uint2(*reinterpret_cast<uint32_t*>(&lo), *reinterpret_cast<uint32_t*>(&hi));
}

// (D,P) fp32 -> (P,D) half
__global__ __launch_bounds__(256) void transpose_h(
    const float* __restrict__ in, __half* __restrict__ out)
{
    __shared__ float t[32][33];
    int tx = threadIdx.x, ty = threadIdx.y;
    int x = blockIdx.x * 32 + tx;
    int y = blockIdx.y * 32 + ty;
#pragma unroll
    for (int j = 0; j < 32; j += 8)
        t[ty + j][tx] = in[(size_t)(y + j) * PP + x];
    __syncthreads();
    int x2 = blockIdx.y * 32 + tx;
    int y2 = blockIdx.x * 32 + ty;
#pragma unroll
    for (int j = 0; j < 32; j += 8)
        out[(size_t)(y2 + j) * DD + x2] = __float2half_rn(t[tx][ty + j]);
}

// ---------------- fp16 mma.sync NT GEMM, 128x128 CTA, BK=64, 3 stages --------
// C[m,n] = sum_k A[m,k] * B[n,k]; A,B half row-major (leading dims in halves).
// 8 warps (4x2), warp tile 32x64, 2 CTAs/SM.
// MODE: 0 plain | 1 causal tile-skip + 1/32 scale on store | 2 K bound m0+128
// OUTH: 1 -> store half, 0 -> store float
#define BK 64
#define ROWB 144               // bytes per smem row (64 halves + 8 pad) = 9 x 16B
#define TILEB 18432            // 128 * 144
#define STAGEB 36864           // A + B
#define SMEM_TOTAL 110592      // 3 stages

template <int MODE, int OUTH>
__global__ void __launch_bounds__(256, 2) gemm_nt_h(
    const __half* __restrict__ A, const __half* __restrict__ B, void* __restrict__ Cv,
    int lda, int ldb, int ldc, int K,
    long long sA, long long sB, long long sC)
{
    const int m0 = blockIdx.y * 128;
    const int n0 = blockIdx.x * 128;
    if (MODE == 1 && n0 > m0) return;

    extern __shared__ char smem[];
    const int bz = blockIdx.z;
    A += (long long)bz * sA;
    B += (long long)bz * sB;

    const int tid = threadIdx.x;
    const int lane = tid & 31;
    const int wid = tid >> 5;
    const int warp_m = wid & 3;        // 4 x 32 rows
    const int warp_n = wid >> 2;       // 2 x 64 cols
    const int g = lane >> 2;           // 0..7
    const int t = lane & 3;            // 0..3

    const uint32_t smb = smem_u32(smem);

    int kend = K;
    if (MODE == 2) { int lim = m0 + 128; kend = (lim < K) ? lim : K; }
    const int T = kend / BK;

    float acc[2][8][4];
#pragma unroll
    for (int mt = 0; mt < 2; mt++)
#pragma unroll
        for (int nt = 0; nt < 8; nt++)
#pragma unroll
            for (int i = 0; i < 4; i++) acc[mt][nt][i] = 0.f;

    // loader: 128 rows x 8 16B-chunks = 1024 chunks per operand; 4/thread each
    const int lrow = tid >> 1;          // 0..127
    const int lc0  = (tid & 1) << 2;    // 0 or 4 (chunk base)
    auto load_tile = [&](int kt, int st) {
        const int k0 = kt * BK;
        const uint32_t dA = smb + (uint32_t)st * STAGEB;
        const uint32_t dB = dA + TILEB;
        const long long arow = (long long)(m0 + lrow) * lda + k0;
        const long long brow = (long long)(n0 + lrow) * ldb + k0;
#pragma unroll
        for (int i = 0; i < 4; i++) {
            int c = lc0 + i;            // chunk 0..7
            uint32_t doff = (uint32_t)(lrow * ROWB + c * 16);
            CP_ASYNC16(dA + doff, &A[arow + c * 8]);
            CP_ASYNC16(dB + doff, &B[brow + c * 8]);
        }
    };

    // prologue: stages 0,1
    if (0 < T) load_tile(0, 0);
    CP_COMMIT();
    if (1 < T) load_tile(1, 1);
    CP_COMMIT();

    const int lr = lane & 15;
    const int lcb = (lane >> 4) * 16;
    const uint32_t aRow = (uint32_t)((warp_m * 32 + lr) * ROWB) + lcb;
    const uint32_t bRow = (uint32_t)((warp_n * 64 + lr) * ROWB) + lcb;

    int st = 0, stn = 2;                // current stage, next-load stage
    for (int kt = 0; kt < T; kt++) {
        CP_WAIT(1);
        __syncthreads();
        if (kt + 2 < T) load_tile(kt + 2, stn);
        CP_COMMIT();

        const uint32_t bufA = smb + (uint32_t)st * STAGEB;
        const uint32_t bufB = bufA + TILEB;

#pragma unroll
        for (int ks = 0; ks < BK; ks += 16) {
            uint32_t a[2][4];
#pragma unroll
            for (int mt = 0; mt < 2; mt++)
                LDSM_X4(a[mt][0], a[mt][1], a[mt][2], a[mt][3],
                        bufA + aRow + (uint32_t)(mt * 16 * ROWB + ks * 2));
            uint32_t b[8][2];
#pragma unroll
            for (int p = 0; p < 4; p++) {
                uint32_t r0, r1, r2, r3;
                LDSM_X4(r0, r1, r2, r3,
                        bufB + bRow + (uint32_t)(p * 16 * ROWB + ks * 2));
                b[2*p][0] = r0; b[2*p+1][0] = r1;
                b[2*p][1] = r2; b[2*p+1][1] = r3;
            }
#pragma unroll
            for (int mt = 0; mt < 2; mt++)
#pragma unroll
                for (int nt = 0; nt < 8; nt++)
                    mma_f16(acc[mt][nt], a[mt], b[nt]);
        }
        st = (st == 2) ? 0 : st + 1;
        stn = (stn == 2) ? 0 : stn + 1;
    }

    // ---- epilogue ----
    if (OUTH) {
        __half* C = reinterpret_cast<__half*>(Cv) + (long long)bz * sC;
#pragma unroll
        for (int mt = 0; mt < 2; mt++) {
            long long r = m0 + warp_m * 32 + mt * 16 + g;
#pragma unroll
            for (int nt = 0; nt < 8; nt++) {
                int c = n0 + warp_n * 64 + nt * 8 + t * 2;
                *reinterpret_cast<__half2*>(&C[r * ldc + c]) =
                    __floats2half2_rn(acc[mt][nt][0], acc[mt][nt][1]);
                *reinterpret_cast<__half2*>(&C[(r + 8) * ldc + c]) =
                    __floats2half2_rn(acc[mt][nt][2], acc[mt][nt][3]);
            }
        }
    } else {
        const float sc = (MODE == 1) ? 0.03125f : 1.0f;
        float* C = reinterpret_cast<float*>(Cv) + (long long)bz * sC;
#pragma unroll
        for (int mt = 0; mt < 2; mt++) {
            long long r = m0 + warp_m * 32 + mt * 16 + g;
#pragma unroll
            for (int nt = 0; nt < 8; nt++) {
                int c = n0 + warp_n * 64 + nt * 8 + t * 2;
                *reinterpret_cast<float2*>(&C[r * ldc + c]) =
                    make_float2(acc[mt][nt][0] * sc, acc[mt][nt][1] * sc);
                *reinterpret_cast<float2*>(&C[(r + 8) * ldc + c]) =
                    make_float2(acc[mt][nt][2] * sc, acc[mt][nt][3] * sc);
            }
        }
    }
}

// ---------------- register-resident causal softmax ---------------------------
// Scores pre-scaled by 1/32. Longest rows scheduled first (s = 2047 - bid).
// Zero tail to 128-block boundary (context kend = m0+128).
__global__ __launch_bounds__(256) void softmax_causal(
    const float* __restrict__ Sc, __half* __restrict__ Ph)
{
    const int r = blockIdx.x;
    const int b = r >> 11;
    const int s = 2047 - (r & 2047);    // longest first
    const float* row = Sc + ((size_t)b * SS + s) * SS;
    __half* prow = Ph + ((size_t)b * SS + s) * SS;
    const int L = s + 1;
    const int Lpad = (L + 127) & ~127;
    const int tid = threadIdx.x;
    const int lane = tid & 31;
    const int wid = tid >> 5;
    __shared__ float red[8];

    float v[8];
    float mx = -1e30f;
#pragma unroll
    for (int j = 0; j < 2; j++) {
        int base = (tid + 256 * j) * 4;
        if (base < L) {
            float4 tv = *reinterpret_cast<const float4*>(row + base);
            v[j*4+0] = tv.x; v[j*4+1] = tv.y; v[j*4+2] = tv.z; v[j*4+3] = tv.w;
#pragma unroll
            for (int e = 0; e < 4; e++)
                if (base + e < L) mx = fmaxf(mx, v[j*4+e]);
        }
    }
#pragma unroll
    for (int o = 16; o > 0; o >>= 1)
        mx = fmaxf(mx, __shfl_xor_sync(0xffffffffu, mx, o));
    if (lane == 0) red[wid] = mx;
    __syncthreads();
    if (wid == 0) {
        float m = red[lane & 7];
#pragma unroll
        for (int o = 4; o > 0; o >>= 1)
            m = fmaxf(m, __shfl_xor_sync(0xffffffffu, m, o));
        if (lane == 0) red[0] = m;
    }
    __syncthreads();
    mx = red[0];

    float sum = 0.f;
#pragma unroll
    for (int j = 0; j < 2; j++) {
        int base = (tid + 256 * j) * 4;
        if (base < L) {
#pragma unroll
            for (int e = 0; e < 4; e++) {
                float ev = (base + e < L) ? __expf(v[j*4+e] - mx) : 0.f;
                v[j*4+e] = ev;
                sum += ev;
            }
        }
    }
#pragma unroll
    for (int o = 16; o > 0; o >>= 1)
        sum += __shfl_xor_sync(0xffffffffu, sum, o);
    __syncthreads();
    if (lane == 0) red[wid] = sum;
    __syncthreads();
    if (wid == 0) {
        float m = red[lane & 7];
#pragma unroll
        for (int o = 4; o > 0; o >>= 1)
            m += __shfl_xor_sync(0xffffffffu, m, o);
        if (lane == 0) red[0] = m;
    }
    __syncthreads();
    const float inv = 1.f / red[0];

#pragma unroll
    for (int j = 0; j < 2; j++) {
        int base = (tid + 256 * j) * 4;
        if (base < Lpad) {
            float e0 = (base < L) ? v[j*4+0] * inv : 0.f;
            float e1 = (base + 1 < L) ? v[j*4+1] * inv : 0.f;
            float e2 = (base + 2 < L) ? v[j*4+2] * inv : 0.f;
            float e3 = (base + 3 < L) ? v[j*4+3] * inv : 0.f;
            __half2 lo = __floats2half2_rn(e0, e1);
            __half2 hi = __floats2half2_rn(e2, e3);
            *reinterpret_cast<uint2*>(prow + base) =
                make_uint2(*reinterpret_cast<uint32_t*>(&lo),
                           *reinterpret_cast<uint32_t*>(&hi));
        }
    }
}

// ---------------- driver ----------------------------------------------------
extern "C" void kernel_launch(void* const* d_in, const int* in_sizes, int n_in,
                              void* d_out, int out_size)
{
    const float* x  = (const float*)d_in[0];
    const float* Wq = (const float*)d_in[1];
    const float* Wk = (const float*)d_in[2];
    const float* Wv = (const float*)d_in[3];
    float* out = (float*)d_out;

    __half *qkh, *vt, *ph, *xh, *wt;
    float* sc;
    cudaGetSymbolAddress((void**)&qkh, g_qkh);
    cudaGetSymbolAddress((void**)&vt,  g_vt);
    cudaGetSymbolAddress((void**)&sc,  g_s);
    cudaGetSymbolAddress((void**)&ph,  g_ph);
    cudaGetSymbolAddress((void**)&xh,  g_xh);
    cudaGetSymbolAddress((void**)&wt,  g_wt);
    __half* wvt = wt + (size_t)2 * PP * DD;

    cudaFuncSetAttribute(gemm_nt_h<0,1>, cudaFuncAttributeMaxDynamicSharedMemorySize, SMEM_TOTAL);
    cudaFuncSetAttribute(gemm_nt_h<1,0>, cudaFuncAttributeMaxDynamicSharedMemorySize, SMEM_TOTAL);
    cudaFuncSetAttribute(gemm_nt_h<2,0>, cudaFuncAttributeMaxDynamicSharedMemorySize, SMEM_TOTAL);

    // 0) conversions
    const int xn4 = (BB * SS * DD) / 4;
    f2h<<<(xn4 + 255) / 256, 256>>>(x, xh, xn4);
    dim3 tb(32, 8), tg(32, 32);
    transpose_h<<<tg, tb>>>(Wq, wt);
    transpose_h<<<tg, tb>>>(Wk, wt + (size_t)PP * DD);
    transpose_h<<<tg, tb>>>(Wv, wvt);

    const long long sSD  = (long long)SS * DD;
    const long long sPS  = (long long)PP * SS;
    const long long sSSq = (long long)SS * SS;
    const long long sQK  = (long long)SS * 2048;
    const long long sSP  = (long long)SS * PP;

    // 1) fused q|k: NT(xh, [Wq^T;Wk^T])  M=B*S, N=2048, K=D
    dim3 gqk(2048 / 128, (BB * SS) / 128, 1);
    gemm_nt_h<0,1><<<gqk, 256, SMEM_TOTAL>>>(xh, wt, qkh, DD, DD, 2048, DD, 0, 0, 0);

    // 2) v^T per batch: NT(Wv^T, xh_b)  M=P, N=S, K=D
    dim3 gv(SS / 128, PP / 128, BB);
    gemm_nt_h<0,1><<<gv, 256, SMEM_TOTAL>>>(wvt, xh, vt, DD, DD, SS, DD, 0, sSD, sPS);

    // 3) scores: NT(q_b, k_b) strided views of qkh; 1/32 folded into store
    dim3 gs(SS / 128, SS / 128, BB);
    gemm_nt_h<1,0><<<gs, 256, SMEM_TOTAL>>>(qkh, qkh + 1024, sc,
                                            2048, 2048, SS, PP, sQK, sQK, sSSq);

    // 4) softmax, half probs + zero tail to 128 boundary, longest rows first
    softmax_causal<<<BB * SS, 256>>>(sc, ph);

    // 5) context: NT(P_b, v^T_b)  M=S, N=P, K bounded at m0+128
    dim3 gc(PP / 128, SS / 128, BB);
    gemm_nt_h<2,0><<<gc, 256, SMEM_TOTAL>>>(ph, vt, out, SS, SS, PP, SS, sSSq, sPS, sSP);
}

// round 15
// speedup vs baseline: 1.1663x; 1.1663x over previous
#include <cuda_runtime.h>
#include <cuda_fp16.h>
#include <cstdint>

#define BB 4
#define SS 2048
#define DD 1024
#define PP 1024

// ---------------- scratch (device globals; no allocation allowed) ----------
__device__ __half g_qh[(size_t)BB * SS * PP];           // (B*S, P)
__device__ __half g_kh[(size_t)BB * SS * PP];
__device__ __half g_vt[(size_t)BB * PP * SS];           // per-batch (P, S)
__device__ float  g_s [(size_t)BB * SS * SS];           // scores fp32 (pre-scaled)
__device__ __half g_ph[(size_t)BB * SS * SS];           // probs half
__device__ __half g_xh[(size_t)BB * SS * DD];           // x in half
__device__ __half g_wt[3][(size_t)PP * DD];             // W^T half

// ---------------- helpers ---------------------------------------------------
__device__ __forceinline__ uint32_t smem_u32(const void* p) {
    uint32_t a;
    asm("{ .reg .u64 t; cvta.to.shared.u64 t, %1; cvt.u32.u64 %0, t; }"
        : "=r"(a) : "l"(p));
    return a;
}

#define CP_ASYNC16(dst_u32, src_ptr) \
    asm volatile("cp.async.cg.shared.global [%0], [%1], 16;" \
                 :: "r"(dst_u32), "l"(src_ptr) : "memory")
#define CP_COMMIT() asm volatile("cp.async.commit_group;" ::: "memory")
#define CP_WAIT(n)  asm volatile("cp.async.wait_group %0;" :: "n"(n) : "memory")

#define LDSM_X4(r0, r1, r2, r3, addr) \
    asm volatile("ldmatrix.sync.aligned.m8n8.x4.shared.b16 {%0,%1,%2,%3}, [%4];" \
                 : "=r"(r0), "=r"(r1), "=r"(r2), "=r"(r3) : "r"(addr))

__device__ __forceinline__ void mma_f16(float* c, const uint32_t* a, const uint32_t* b) {
    asm volatile(
        "mma.sync.aligned.m16n8k16.row.col.f32.f16.f16.f32 "
        "{%0,%1,%2,%3}, {%4,%5,%6,%7}, {%8,%9}, {%0,%1,%2,%3};"
        : "+f"(c[0]), "+f"(c[1]), "+f"(c[2]), "+f"(c[3])
        : "r"(a[0]), "r"(a[1]), "r"(a[2]), "r"(a[3]), "r"(b[0]), "r"(b[1]));
}

// ---------------- conversion kernels ----------------------------------------
__global__ __launch_bounds__(256) void f2h(
    const float* __restrict__ in, __half* __restrict__ out, int n4)
{
    int i = blockIdx.x * 256 + threadIdx.x;
    if (i >= n4) return;
    float4 v = reinterpret_cast<const float4*>(in)[i];
    __half2 lo = __floats2half2_rn(v.x, v.y);
    __half2 hi = __floats2half2_rn(v.z, v.w);
    reinterpret_cast<uint2*>(out)[i] =
        make_uint2(*reinterpret_cast<uint32_t*>(&lo), *reinterpret_cast<uint32_t*>(&hi));
}

// (D,P) fp32 -> (P,D) half
__global__ __launch_bounds__(256) void transpose_h(
    const float* __restrict__ in, __half* __restrict__ out)
{
    __shared__ float t[32][33];
    int tx = threadIdx.x, ty = threadIdx.y;
    int x = blockIdx.x * 32 + tx;
    int y = blockIdx.y * 32 + ty;
#pragma unroll
    for (int j = 0; j < 32; j += 8)
        t[ty + j][tx] = in[(size_t)(y + j) * PP + x];
    __syncthreads();
    int x2 = blockIdx.y * 32 + tx;
    int y2 = blockIdx.x * 32 + ty;
#pragma unroll
    for (int j = 0; j < 32; j += 8)
        out[(size_t)(y2 + j) * DD + x2] = __float2half_rn(t[tx][ty + j]);
}

// ---------------- fp16 mma.sync NT GEMM (R8 config) --------------------------
// C[m,n] = sum_k A[m,k] * B[n,k]; A,B half row-major, leading dim in halves.
// 128x128 CTA tile, BK=32, 4 stages, 256 threads (8 warps 4x2, warp 32x64).
// MODE: 0 plain | 1 causal tile-skip + 1/32 scale on store | 2 K bound m0+128
// OUTH: 1 -> store half, 0 -> store float
#define BK 32
#define TILEB 10240            // 128 rows * 80 B (40 halves padded)
#define STAGEB 20480           // A + B
#define SMEM_TOTAL 81920       // 4 stages

template <int MODE, int OUTH>
__global__ void __launch_bounds__(256, 2) gemm_nt_h(
    const __half* __restrict__ A, const __half* __restrict__ B, void* __restrict__ Cv,
    int lda, int ldb, int ldc, int K,
    long long sA, long long sB, long long sC)
{
    const int m0 = blockIdx.y * 128;
    const int n0 = blockIdx.x * 128;
    if (MODE == 1 && n0 > m0) return;

    extern __shared__ char smem[];
    const int bz = blockIdx.z;
    A += (long long)bz * sA;
    B += (long long)bz * sB;

    const int tid = threadIdx.x;
    const int lane = tid & 31;
    const int wid = tid >> 5;
    const int warp_m = wid & 3;        // 32 rows each
    const int warp_n = wid >> 2;       // 64 cols each
    const int g = lane >> 2;           // 0..7
    const int t = lane & 3;            // 0..3

    const uint32_t smb = smem_u32(smem);

    int kend = K;
    if (MODE == 2) { int lim = m0 + 128; kend = (lim < K) ? lim : K; }
    const int T = kend / BK;

    float acc[2][8][4];
#pragma unroll
    for (int mt = 0; mt < 2; mt++)
#pragma unroll
        for (int nt = 0; nt < 8; nt++)
#pragma unroll
            for (int i = 0; i < 4; i++) acc[mt][nt][i] = 0.f;

    // tile loader: stage kt&3; 2 x (A+B) float4 per thread
    const int ldrow = tid >> 2;         // 0..63 (+64 second iter)
    const int ldc4  = tid & 3;
    auto load_tile = [&](int kt) {
        const int k0 = kt * BK;
        const uint32_t dA = smb + (kt & 3) * STAGEB;
        const uint32_t dB = dA + TILEB;
#pragma unroll
        for (int i = 0; i < 2; i++) {
            int row = ldrow + i * 64;
            uint32_t doff = (uint32_t)(row * 80 + ldc4 * 16);
            CP_ASYNC16(dA + doff, &A[(long long)(m0 + row) * lda + k0 + ldc4 * 8]);
            CP_ASYNC16(dB + doff, &B[(long long)(n0 + row) * ldb + k0 + ldc4 * 8]);
        }
    };

    // prologue: stages 0,1,2 (always commit to keep group count uniform)
#pragma unroll
    for (int p = 0; p < 3; p++) { if (p < T) load_tile(p); CP_COMMIT(); }

    const int lr = lane & 15;
    const int lcb = (lane >> 4) * 16;
    const uint32_t aRow = (uint32_t)((warp_m * 32 + lr) * 80) + lcb;
    const uint32_t bRow = (uint32_t)((warp_n * 64 + lr) * 80) + lcb;

    for (int kt = 0; kt < T; kt++) {
        CP_WAIT(2);
        __syncthreads();
        if (kt + 3 < T) load_tile(kt + 3);
        CP_COMMIT();

        const uint32_t bufA = smb + (kt & 3) * STAGEB;
        const uint32_t bufB = bufA + TILEB;

#pragma unroll
        for (int ks = 0; ks < BK; ks += 16) {
            uint32_t a[2][4];
#pragma unroll
            for (int mt = 0; mt < 2; mt++)
                LDSM_X4(a[mt][0], a[mt][1], a[mt][2], a[mt][3],
                        bufA + aRow + (uint32_t)(mt * 16 * 80 + ks * 2));
            uint32_t b[8][2];
#pragma unroll
            for (int p = 0; p < 4; p++) {
                uint32_t r0, r1, r2, r3;
                LDSM_X4(r0, r1, r2, r3,
                        bufB + bRow + (uint32_t)(p * 16 * 80 + ks * 2));
                b[2*p][0] = r0; b[2*p+1][0] = r1;
                b[2*p][1] = r2; b[2*p+1][1] = r3;
            }
#pragma unroll
            for (int mt = 0; mt < 2; mt++)
#pragma unroll
                for (int nt = 0; nt < 8; nt++)
                    mma_f16(acc[mt][nt], a[mt], b[nt]);
        }
    }

    // ---- epilogue ----
    if (OUTH) {
        __half* C = reinterpret_cast<__half*>(Cv) + (long long)bz * sC;
#pragma unroll
        for (int mt = 0; mt < 2; mt++) {
            long long r = m0 + warp_m * 32 + mt * 16 + g;
#pragma unroll
            for (int nt = 0; nt < 8; nt++) {
                int c = n0 + warp_n * 64 + nt * 8 + t * 2;
                *reinterpret_cast<__half2*>(&C[r * ldc + c]) =
                    __floats2half2_rn(acc[mt][nt][0], acc[mt][nt][1]);
                *reinterpret_cast<__half2*>(&C[(r + 8) * ldc + c]) =
                    __floats2half2_rn(acc[mt][nt][2], acc[mt][nt][3]);
            }
        }
    } else {
        const float sc = (MODE == 1) ? 0.03125f : 1.0f;
        float* C = reinterpret_cast<float*>(Cv) + (long long)bz * sC;
#pragma unroll
        for (int mt = 0; mt < 2; mt++) {
            long long r = m0 + warp_m * 32 + mt * 16 + g;
#pragma unroll
            for (int nt = 0; nt < 8; nt++) {
                int c = n0 + warp_n * 64 + nt * 8 + t * 2;
                *reinterpret_cast<float2*>(&C[r * ldc + c]) =
                    make_float2(acc[mt][nt][0] * sc, acc[mt][nt][1] * sc);
                *reinterpret_cast<float2*>(&C[(r + 8) * ldc + c]) =
                    make_float2(acc[mt][nt][2] * sc, acc[mt][nt][3] * sc);
            }
        }
    }
}

// ---------------- register-resident causal softmax ---------------------------
// Scores pre-scaled by 1/32. Longest rows first (s = 2047 - bid).
// Writes half probs + zero tail to 128-block boundary (context kend = m0+128).
__global__ __launch_bounds__(256) void softmax_causal(
    const float* __restrict__ Sc, __half* __restrict__ Ph)
{
    const int r = blockIdx.x;
    const int b = r >> 11;
    const int s = 2047 - (r & 2047);    // longest first
    const float* row = Sc + ((size_t)b * SS + s) * SS;
    __half* prow = Ph + ((size_t)b * SS + s) * SS;
    const int L = s + 1;
    const int Lpad = (L + 127) & ~127;
    const int tid = threadIdx.x;
    const int lane = tid & 31;
    const int wid = tid >> 5;
    __shared__ float red[8];

    float v[8];
    float mx = -1e30f;
#pragma unroll
    for (int j = 0; j < 2; j++) {
        int base = (tid + 256 * j) * 4;
        if (base < L) {
            float4 tv = *reinterpret_cast<const float4*>(row + base);
            v[j*4+0] = tv.x; v[j*4+1] = tv.y; v[j*4+2] = tv.z; v[j*4+3] = tv.w;
#pragma unroll
            for (int e = 0; e < 4; e++)
                if (base + e < L) mx = fmaxf(mx, v[j*4+e]);
        }
    }
#pragma unroll
    for (int o = 16; o > 0; o >>= 1)
        mx = fmaxf(mx, __shfl_xor_sync(0xffffffffu, mx, o));
    if (lane == 0) red[wid] = mx;
    __syncthreads();
    if (wid == 0) {
        float m = red[lane & 7];
#pragma unroll
        for (int o = 4; o > 0; o >>= 1)
            m = fmaxf(m, __shfl_xor_sync(0xffffffffu, m, o));
        if (lane == 0) red[0] = m;
    }
    __syncthreads();
    mx = red[0];

    float sum = 0.f;
#pragma unroll
    for (int j = 0; j < 2; j++) {
        int base = (tid + 256 * j) * 4;
        if (base < L) {
#pragma unroll
            for (int e = 0; e < 4; e++) {
                float ev = (base + e < L) ? __expf(v[j*4+e] - mx) : 0.f;
                v[j*4+e] = ev;
                sum += ev;
            }
        }
    }
#pragma unroll
    for (int o = 16; o > 0; o >>= 1)
        sum += __shfl_xor_sync(0xffffffffu, sum, o);
    __syncthreads();
    if (lane == 0) red[wid] = sum;
    __syncthreads();
    if (wid == 0) {
        float m = red[lane & 7];
#pragma unroll
        for (int o = 4; o > 0; o >>= 1)
            m += __shfl_xor_sync(0xffffffffu, m, o);
        if (lane == 0) red[0] = m;
    }
    __syncthreads();
    const float inv = 1.f / red[0];

#pragma unroll
    for (int j = 0; j < 2; j++) {
        int base = (tid + 256 * j) * 4;
        if (base < Lpad) {
            float e0 = (base < L) ? v[j*4+0] * inv : 0.f;
            float e1 = (base + 1 < L) ? v[j*4+1] * inv : 0.f;
            float e2 = (base + 2 < L) ? v[j*4+2] * inv : 0.f;
            float e3 = (base + 3 < L) ? v[j*4+3] * inv : 0.f;
            __half2 lo = __floats2half2_rn(e0, e1);
            __half2 hi = __floats2half2_rn(e2, e3);
            *reinterpret_cast<uint2*>(prow + base) =
                make_uint2(*reinterpret_cast<uint32_t*>(&lo),
                           *reinterpret_cast<uint32_t*>(&hi));
        }
    }
}

// ---------------- driver ----------------------------------------------------
extern "C" void kernel_launch(void* const* d_in, const int* in_sizes, int n_in,
                              void* d_out, int out_size)
{
    const float* x  = (const float*)d_in[0];
    const float* Wq = (const float*)d_in[1];
    const float* Wk = (const float*)d_in[2];
    const float* Wv = (const float*)d_in[3];
    float* out = (float*)d_out;

    __half *qh, *kh, *vt, *ph, *xh, *wt;
    float* sc;
    cudaGetSymbolAddress((void**)&qh, g_qh);
    cudaGetSymbolAddress((void**)&kh, g_kh);
    cudaGetSymbolAddress((void**)&vt, g_vt);
    cudaGetSymbolAddress((void**)&sc, g_s);
    cudaGetSymbolAddress((void**)&ph, g_ph);
    cudaGetSymbolAddress((void**)&xh, g_xh);
    cudaGetSymbolAddress((void**)&wt, g_wt);
    __half* wqt = wt;
    __half* wkt = wt + (size_t)PP * DD;
    __half* wvt = wt + (size_t)2 * PP * DD;

    cudaFuncSetAttribute(gemm_nt_h<0,1>, cudaFuncAttributeMaxDynamicSharedMemorySize, SMEM_TOTAL);
    cudaFuncSetAttribute(gemm_nt_h<1,0>, cudaFuncAttributeMaxDynamicSharedMemorySize, SMEM_TOTAL);
    cudaFuncSetAttribute(gemm_nt_h<2,0>, cudaFuncAttributeMaxDynamicSharedMemorySize, SMEM_TOTAL);

    // 0) conversions: x -> half, W -> transposed half
    const int xn4 = (BB * SS * DD) / 4;
    f2h<<<(xn4 + 255) / 256, 256>>>(x, xh, xn4);
    dim3 tb(32, 8), tg(32, 32);
    transpose_h<<<tg, tb>>>(Wq, wqt);
    transpose_h<<<tg, tb>>>(Wk, wkt);
    transpose_h<<<tg, tb>>>(Wv, wvt);

    const long long sSP  = (long long)SS * PP;
    const long long sSD  = (long long)SS * DD;
    const long long sPS  = (long long)PP * SS;
    const long long sSSq = (long long)SS * SS;

    // 1) q, k: NT(xh, W^T)  M=B*S, N=P, K=D
    dim3 gp(PP / 128, (BB * SS) / 128, 1);
    gemm_nt_h<0,1><<<gp, 256, SMEM_TOTAL>>>(xh, wqt, qh, DD, DD, PP, DD, 0, 0, 0);
    gemm_nt_h<0,1><<<gp, 256, SMEM_TOTAL>>>(xh, wkt, kh, DD, DD, PP, DD, 0, 0, 0);

    // 2) v^T per batch: NT(Wv^T, xh_b)  M=P, N=S, K=D
    dim3 gv(SS / 128, PP / 128, BB);
    gemm_nt_h<0,1><<<gv, 256, SMEM_TOTAL>>>(wvt, xh, vt, DD, DD, SS, DD, 0, sSD, sPS);

    // 3) scores: NT(q_b, k_b)  M=S, N=S, K=P, causal skip, 1/32 on store
    dim3 gs(SS / 128, SS / 128, BB);
    gemm_nt_h<1,0><<<gs, 256, SMEM_TOTAL>>>(qh, kh, sc, PP, PP, SS, PP, sSP, sSP, sSSq);

    // 4) softmax, half probs + zero tail, longest rows first
    softmax_causal<<<BB * SS, 256>>>(sc, ph);

    // 5) context: NT(P_b, v^T_b)  M=S, N=P, K bounded at m0+128
    dim3 gc(PP / 128, SS / 128, BB);
    gemm_nt_h<2,0><<<gc, 256, SMEM_TOTAL>>>(ph, vt, out, SS, SS, PP, SS, sSSq, sPS, sSP);
}

// round 16
// speedup vs baseline: 1.1771x; 1.0093x over previous
#include <cuda_runtime.h>
#include <cuda_fp16.h>
#include <cstdint>

#define BB 4
#define SS 2048
#define DD 1024
#define PP 1024

// ---------------- scratch (device globals; no allocation allowed) ----------
__device__ __half g_qh[(size_t)BB * SS * PP];           // (B*S, P)
__device__ __half g_kh[(size_t)BB * SS * PP];
__device__ __half g_vt[(size_t)BB * PP * SS];           // per-batch (P, S)
__device__ float  g_s [(size_t)BB * SS * SS];           // scores fp32 (pre-scaled)
__device__ __half g_ph[(size_t)BB * SS * SS];           // probs half
__device__ __half g_xh[(size_t)BB * SS * DD];           // x in half
__device__ __half g_wt[3][(size_t)PP * DD];             // W^T half

// ---------------- helpers ---------------------------------------------------
__device__ __forceinline__ uint32_t smem_u32(const void* p) {
    uint32_t a;
    asm("{ .reg .u64 t; cvta.to.shared.u64 t, %1; cvt.u32.u64 %0, t; }"
        : "=r"(a) : "l"(p));
    return a;
}

#define CP_ASYNC16(dst_u32, src_ptr) \
    asm volatile("cp.async.cg.shared.global [%0], [%1], 16;" \
                 :: "r"(dst_u32), "l"(src_ptr) : "memory")
#define CP_COMMIT() asm volatile("cp.async.commit_group;" ::: "memory")
#define CP_WAIT(n)  asm volatile("cp.async.wait_group %0;" :: "n"(n) : "memory")

#define LDSM_X4(r0, r1, r2, r3, addr) \
    asm volatile("ldmatrix.sync.aligned.m8n8.x4.shared.b16 {%0,%1,%2,%3}, [%4];" \
                 : "=r"(r0), "=r"(r1), "=r"(r2), "=r"(r3) : "r"(addr))

__device__ __forceinline__ void mma_f16(float* c, const uint32_t* a, const uint32_t* b) {
    asm volatile(
        "mma.sync.aligned.m16n8k16.row.col.f32.f16.f16.f32 "
        "{%0,%1,%2,%3}, {%4,%5,%6,%7}, {%8,%9}, {%0,%1,%2,%3};"
        : "+f"(c[0]), "+f"(c[1]), "+f"(c[2]), "+f"(c[3])
        : "r"(a[0]), "r"(a[1]), "r"(a[2]), "r"(a[3]), "r"(b[0]), "r"(b[1]));
}

// ---------------- fused prep: x->half + 3 weight transposes ------------------
// blocks [0, 8192)          : x fp32 -> half (float4 granularity)
// blocks [8192, 8192+3072)  : W (D,P) fp32 -> W^T (P,D) half, 32x32 tiles
__global__ __launch_bounds__(256) void prep(
    const float* __restrict__ x,
    const float* __restrict__ Wq, const float* __restrict__ Wk,
    const float* __restrict__ Wv,
    __half* __restrict__ xh,
    __half* __restrict__ wqt, __half* __restrict__ wkt, __half* __restrict__ wvt)
{
    const int bid = blockIdx.x;
    if (bid < 8192) {
        int i = bid * 256 + threadIdx.x;        // < 2,097,152 float4s
        float4 v = reinterpret_cast<const float4*>(x)[i];
        __half2 lo = __floats2half2_rn(v.x, v.y);
        __half2 hi = __floats2half2_rn(v.z, v.w);
        reinterpret_cast<uint2*>(xh)[i] =
            make_uint2(*reinterpret_cast<uint32_t*>(&lo), *reinterpret_cast<uint32_t*>(&hi));
        return;
    }
    __shared__ float t[32][33];
    const int tb = bid - 8192;                  // 0..3071
    const int w = tb >> 10;                     // which W
    const int tile = tb & 1023;                 // 0..1023 (32x32 tile grid)
    const float* in = (w == 0) ? Wq : (w == 1) ? Wk : Wv;
    __half* out = (w == 0) ? wqt : (w == 1) ? wkt : wvt;
    const int bx = tile & 31, by = tile >> 5;
    const int tx = threadIdx.x & 31, ty = threadIdx.x >> 5;   // ty 0..7
    const int xcol = bx * 32 + tx;              // P col of in
    const int yrow = by * 32 + ty;              // D row of in
#pragma unroll
    for (int j = 0; j < 32; j += 8)
        t[ty + j][tx] = in[(size_t)(yrow + j) * PP + xcol];
    __syncthreads();
    const int x2 = by * 32 + tx;                // D col of out
    const int y2 = bx * 32 + ty;                // P row of out
#pragma unroll
    for (int j = 0; j < 32; j += 8)
        out[(size_t)(y2 + j) * DD + x2] = __float2half_rn(t[tx][ty + j]);
}

// ---------------- fp16 mma.sync NT GEMM (proven R8 config) -------------------
// C[m,n] = sum_k A[m,k] * B[n,k]; A,B half row-major, leading dim in halves.
// 128x128 CTA tile, BK=32, 4 stages, 256 threads (8 warps 4x2, warp 32x64).
// MODE: 0 plain | 1 triangular grid (blockIdx.x = packed tile) + 1/32 scale
//       | 2 K bound m0+128
// OUTH: 1 -> store half, 0 -> store float
#define BK 32
#define TILEB 10240            // 128 rows * 80 B (40 halves padded)
#define STAGEB 20480           // A + B
#define SMEM_TOTAL 81920       // 4 stages

template <int MODE, int OUTH>
__global__ void __launch_bounds__(256, 2) gemm_nt_h(
    const __half* __restrict__ A, const __half* __restrict__ B, void* __restrict__ Cv,
    int lda, int ldb, int ldc, int K,
    long long sA, long long sB, long long sC)
{
    int m0, n0;
    if (MODE == 1) {
        // triangular decode: blockIdx.x in [0,136) -> (i,j), j<=i
        const int tt = blockIdx.x;
        int i = (int)((sqrtf(8.0f * tt + 1.0f) - 1.0f) * 0.5f);
        while ((i + 1) * (i + 2) / 2 <= tt) i++;
        while (i * (i + 1) / 2 > tt) i--;
        const int j = tt - i * (i + 1) / 2;
        m0 = i * 128;
        n0 = j * 128;
    } else {
        m0 = blockIdx.y * 128;
        n0 = blockIdx.x * 128;
    }

    extern __shared__ char smem[];
    const int bz = blockIdx.z;
    A += (long long)bz * sA;
    B += (long long)bz * sB;

    const int tid = threadIdx.x;
    const int lane = tid & 31;
    const int wid = tid >> 5;
    const int warp_m = wid & 3;        // 32 rows each
    const int warp_n = wid >> 2;       // 64 cols each
    const int g = lane >> 2;           // 0..7
    const int t = lane & 3;            // 0..3

    const uint32_t smb = smem_u32(smem);

    int kend = K;
    if (MODE == 2) { int lim = m0 + 128; kend = (lim < K) ? lim : K; }
    const int T = kend / BK;

    float acc[2][8][4];
#pragma unroll
    for (int mt = 0; mt < 2; mt++)
#pragma unroll
        for (int nt = 0; nt < 8; nt++)
#pragma unroll
            for (int i = 0; i < 4; i++) acc[mt][nt][i] = 0.f;

    // tile loader: stage kt&3; 2 x (A+B) float4 per thread
    const int ldrow = tid >> 2;         // 0..63 (+64 second iter)
    const int ldc4  = tid & 3;
    auto load_tile = [&](int kt) {
        const int k0 = kt * BK;
        const uint32_t dA = smb + (kt & 3) * STAGEB;
        const uint32_t dB = dA + TILEB;
#pragma unroll
        for (int i = 0; i < 2; i++) {
            int row = ldrow + i * 64;
            uint32_t doff = (uint32_t)(row * 80 + ldc4 * 16);
            CP_ASYNC16(dA + doff, &A[(long long)(m0 + row) * lda + k0 + ldc4 * 8]);
            CP_ASYNC16(dB + doff, &B[(long long)(n0 + row) * ldb + k0 + ldc4 * 8]);
        }
    };

    // prologue: stages 0,1,2 (always commit to keep group count uniform)
#pragma unroll
    for (int p = 0; p < 3; p++) { if (p < T) load_tile(p); CP_COMMIT(); }

    const int lr = lane & 15;
    const int lcb = (lane >> 4) * 16;
    const uint32_t aRow = (uint32_t)((warp_m * 32 + lr) * 80) + lcb;
    const uint32_t bRow = (uint32_t)((warp_n * 64 + lr) * 80) + lcb;

    for (int kt = 0; kt < T; kt++) {
        CP_WAIT(2);
        __syncthreads();
        if (kt + 3 < T) load_tile(kt + 3);
        CP_COMMIT();

        const uint32_t bufA = smb + (kt & 3) * STAGEB;
        const uint32_t bufB = bufA + TILEB;

#pragma unroll
        for (int ks = 0; ks < BK; ks += 16) {
            uint32_t a[2][4];
#pragma unroll
            for (int mt = 0; mt < 2; mt++)
                LDSM_X4(a[mt][0], a[mt][1], a[mt][2], a[mt][3],
                        bufA + aRow + (uint32_t)(mt * 16 * 80 + ks * 2));
            uint32_t b[8][2];
#pragma unroll
            for (int p = 0; p < 4; p++) {
                uint32_t r0, r1, r2, r3;
                LDSM_X4(r0, r1, r2, r3,
                        bufB + bRow + (uint32_t)(p * 16 * 80 + ks * 2));
                b[2*p][0] = r0; b[2*p+1][0] = r1;
                b[2*p][1] = r2; b[2*p+1][1] = r3;
            }
#pragma unroll
            for (int mt = 0; mt < 2; mt++)
#pragma unroll
                for (int nt = 0; nt < 8; nt++)
                    mma_f16(acc[mt][nt], a[mt], b[nt]);
        }
    }

    // ---- epilogue ----
    if (OUTH) {
        __half* C = reinterpret_cast<__half*>(Cv) + (long long)bz * sC;
#pragma unroll
        for (int mt = 0; mt < 2; mt++) {
            long long r = m0 + warp_m * 32 + mt * 16 + g;
#pragma unroll
            for (int nt = 0; nt < 8; nt++) {
                int c = n0 + warp_n * 64 + nt * 8 + t * 2;
                *reinterpret_cast<__half2*>(&C[r * ldc + c]) =
                    __floats2half2_rn(acc[mt][nt][0], acc[mt][nt][1]);
                *reinterpret_cast<__half2*>(&C[(r + 8) * ldc + c]) =
                    __floats2half2_rn(acc[mt][nt][2], acc[mt][nt][3]);
            }
        }
    } else {
        const float sc = (MODE == 1) ? 0.03125f : 1.0f;
        float* C = reinterpret_cast<float*>(Cv) + (long long)bz * sC;
#pragma unroll
        for (int mt = 0; mt < 2; mt++) {
            long long r = m0 + warp_m * 32 + mt * 16 + g;
#pragma unroll
            for (int nt = 0; nt < 8; nt++) {
                int c = n0 + warp_n * 64 + nt * 8 + t * 2;
                *reinterpret_cast<float2*>(&C[r * ldc + c]) =
                    make_float2(acc[mt][nt][0] * sc, acc[mt][nt][1] * sc);
                *reinterpret_cast<float2*>(&C[(r + 8) * ldc + c]) =
                    make_float2(acc[mt][nt][2] * sc, acc[mt][nt][3] * sc);
            }
        }
    }
}

// ---------------- register-resident causal softmax ---------------------------
// Scores pre-scaled by 1/32. Longest rows first (s = 2047 - bid).
// Writes half probs + zero tail to 128-block boundary (context kend = m0+128).
__global__ __launch_bounds__(256) void softmax_causal(
    const float* __restrict__ Sc, __half* __restrict__ Ph)
{
    const int r = blockIdx.x;
    const int b = r >> 11;
    const int s = 2047 - (r & 2047);    // longest first
    const float* row = Sc + ((size_t)b * SS + s) * SS;
    __half* prow = Ph + ((size_t)b * SS + s) * SS;
    const int L = s + 1;
    const int Lpad = (L + 127) & ~127;
    const int tid = threadIdx.x;
    const int lane = tid & 31;
    const int wid = tid >> 5;
    __shared__ float red[8];

    float v[8];
    float mx = -1e30f;
#pragma unroll
    for (int j = 0; j < 2; j++) {
        int base = (tid + 256 * j) * 4;
        if (base < L) {
            float4 tv = *reinterpret_cast<const float4*>(row + base);
            v[j*4+0] = tv.x; v[j*4+1] = tv.y; v[j*4+2] = tv.z; v[j*4+3] = tv.w;
#pragma unroll
            for (int e = 0; e < 4; e++)
                if (base + e < L) mx = fmaxf(mx, v[j*4+e]);
        }
    }
#pragma unroll
    for (int o = 16; o > 0; o >>= 1)
        mx = fmaxf(mx, __shfl_xor_sync(0xffffffffu, mx, o));
    if (lane == 0) red[wid] = mx;
    __syncthreads();
    if (wid == 0) {
        float m = red[lane & 7];
#pragma unroll
        for (int o = 4; o > 0; o >>= 1)
            m = fmaxf(m, __shfl_xor_sync(0xffffffffu, m, o));
        if (lane == 0) red[0] = m;
    }
    __syncthreads();
    mx = red[0];

    float sum = 0.f;
#pragma unroll
    for (int j = 0; j < 2; j++) {
        int base = (tid + 256 * j) * 4;
        if (base < L) {
#pragma unroll
            for (int e = 0; e < 4; e++) {
                float ev = (base + e < L) ? __expf(v[j*4+e] - mx) : 0.f;
                v[j*4+e] = ev;
                sum += ev;
            }
        }
    }
#pragma unroll
    for (int o = 16; o > 0; o >>= 1)
        sum += __shfl_xor_sync(0xffffffffu, sum, o);
    __syncthreads();
    if (lane == 0) red[wid] = sum;
    __syncthreads();
    if (wid == 0) {
        float m = red[lane & 7];
#pragma unroll
        for (int o = 4; o > 0; o >>= 1)
            m += __shfl_xor_sync(0xffffffffu, m, o);
        if (lane == 0) red[0] = m;
    }
    __syncthreads();
    const float inv = 1.f / red[0];

#pragma unroll
    for (int j = 0; j < 2; j++) {
        int base = (tid + 256 * j) * 4;
        if (base < Lpad) {
            float e0 = (base < L) ? v[j*4+0] * inv : 0.f;
            float e1 = (base + 1 < L) ? v[j*4+1] * inv : 0.f;
            float e2 = (base + 2 < L) ? v[j*4+2] * inv : 0.f;
            float e3 = (base + 3 < L) ? v[j*4+3] * inv : 0.f;
            __half2 lo = __floats2half2_rn(e0, e1);
            __half2 hi = __floats2half2_rn(e2, e3);
            *reinterpret_cast<uint2*>(prow + base) =
                make_uint2(*reinterpret_cast<uint32_t*>(&lo),
                           *reinterpret_cast<uint32_t*>(&hi));
        }
    }
}

// ---------------- driver ----------------------------------------------------
extern "C" void kernel_launch(void* const* d_in, const int* in_sizes, int n_in,
                              void* d_out, int out_size)
{
    const float* x  = (const float*)d_in[0];
    const float* Wq = (const float*)d_in[1];
    const float* Wk = (const float*)d_in[2];
    const float* Wv = (const float*)d_in[3];
    float* out = (float*)d_out;

    __half *qh, *kh, *vt, *ph, *xh, *wt;
    float* sc;
    cudaGetSymbolAddress((void**)&qh, g_qh);
    cudaGetSymbolAddress((void**)&kh, g_kh);
    cudaGetSymbolAddress((void**)&vt, g_vt);
    cudaGetSymbolAddress((void**)&sc, g_s);
    cudaGetSymbolAddress((void**)&ph, g_ph);
    cudaGetSymbolAddress((void**)&xh, g_xh);
    cudaGetSymbolAddress((void**)&wt, g_wt);
    __half* wqt = wt;
    __half* wkt = wt + (size_t)PP * DD;
    __half* wvt = wt + (size_t)2 * PP * DD;

    cudaFuncSetAttribute(gemm_nt_h<0,1>, cudaFuncAttributeMaxDynamicSharedMemorySize, SMEM_TOTAL);
    cudaFuncSetAttribute(gemm_nt_h<1,0>, cudaFuncAttributeMaxDynamicSharedMemorySize, SMEM_TOTAL);
    cudaFuncSetAttribute(gemm_nt_h<2,0>, cudaFuncAttributeMaxDynamicSharedMemorySize, SMEM_TOTAL);

    // 0) fused prep: x -> half + 3 weight transposes (one launch)
    prep<<<8192 + 3072, 256>>>(x, Wq, Wk, Wv, xh, wqt, wkt, wvt);

    const long long sSP  = (long long)SS * PP;
    const long long sSD  = (long long)SS * DD;
    const long long sPS  = (long long)PP * SS;
    const long long sSSq = (long long)SS * SS;

    // 1) q, k: NT(xh, W^T)  M=B*S, N=P, K=D
    dim3 gp(PP / 128, (BB * SS) / 128, 1);
    gemm_nt_h<0,1><<<gp, 256, SMEM_TOTAL>>>(xh, wqt, qh, DD, DD, PP, DD, 0, 0, 0);
    gemm_nt_h<0,1><<<gp, 256, SMEM_TOTAL>>>(xh, wkt, kh, DD, DD, PP, DD, 0, 0, 0);

    // 2) v^T per batch: NT(Wv^T, xh_b)  M=P, N=S, K=D
    dim3 gv(SS / 128, PP / 128, BB);
    gemm_nt_h<0,1><<<gv, 256, SMEM_TOTAL>>>(wvt, xh, vt, DD, DD, SS, DD, 0, sSD, sPS);

    // 3) scores: NT(q_b, k_b), triangular-packed grid (136 tiles/batch),
    //    1/32 folded into store
    dim3 gs(136, 1, BB);
    gemm_nt_h<1,0><<<gs, 256, SMEM_TOTAL>>>(qh, kh, sc, PP, PP, SS, PP, sSP, sSP, sSSq);

    // 4) softmax, half probs + zero tail, longest rows first
    softmax_causal<<<BB * SS, 256>>>(sc, ph);

    // 5) context: NT(P_b, v^T_b)  M=S, N=P, K bounded at m0+128
    dim3 gc(PP / 128, SS / 128, BB);
    gemm_nt_h<2,0><<<gc, 256, SMEM_TOTAL>>>(ph, vt, out, SS, SS, PP, SS, sSSq, sPS, sSP);
}

// round 17
// speedup vs baseline: 1.1889x; 1.0100x over previous
#include <cuda_runtime.h>
#include <cuda_fp16.h>
#include <cstdint>

#define BB 4
#define SS 2048
#define DD 1024
#define PP 1024

// ---------------- scratch (device globals; no allocation allowed) ----------
__device__ __half g_qh[(size_t)BB * SS * PP];           // (B*S, P)
__device__ __half g_kh[(size_t)BB * SS * PP];
__device__ __half g_vt[(size_t)BB * PP * SS];           // per-batch (P, S)
__device__ __half g_ph[(size_t)BB * SS * SS];           // unnormalized exp(logit), half
__device__ float  g_rsum[(size_t)BB * SS];              // per-row sums of half-rounded E
__device__ __half g_xh[(size_t)BB * SS * DD];           // x in half
__device__ __half g_wt[3][(size_t)PP * DD];             // W^T half

// ---------------- helpers ---------------------------------------------------
__device__ __forceinline__ uint32_t smem_u32(const void* p) {
    uint32_t a;
    asm("{ .reg .u64 t; cvta.to.shared.u64 t, %1; cvt.u32.u64 %0, t; }"
        : "=r"(a) : "l"(p));
    return a;
}

#define CP_ASYNC16(dst_u32, src_ptr) \
    asm volatile("cp.async.cg.shared.global [%0], [%1], 16;" \
                 :: "r"(dst_u32), "l"(src_ptr) : "memory")
#define CP_COMMIT() asm volatile("cp.async.commit_group;" ::: "memory")
#define CP_WAIT(n)  asm volatile("cp.async.wait_group %0;" :: "n"(n) : "memory")

#define LDSM_X4(r0, r1, r2, r3, addr) \
    asm volatile("ldmatrix.sync.aligned.m8n8.x4.shared.b16 {%0,%1,%2,%3}, [%4];" \
                 : "=r"(r0), "=r"(r1), "=r"(r2), "=r"(r3) : "r"(addr))

__device__ __forceinline__ void mma_f16(float* c, const uint32_t* a, const uint32_t* b) {
    asm volatile(
        "mma.sync.aligned.m16n8k16.row.col.f32.f16.f16.f32 "
        "{%0,%1,%2,%3}, {%4,%5,%6,%7}, {%8,%9}, {%0,%1,%2,%3};"
        : "+f"(c[0]), "+f"(c[1]), "+f"(c[2]), "+f"(c[3])
        : "r"(a[0]), "r"(a[1]), "r"(a[2]), "r"(a[3]), "r"(b[0]), "r"(b[1]));
}

// ---------------- fused prep: x->half + 3 W transposes + rsum zero ----------
// blocks [0, 8192)       : x fp32 -> half (float4 granularity)
// blocks [8192, 11264)   : W (D,P) fp32 -> W^T (P,D) half, 32x32 tiles
// blocks [11264, 11272)  : zero g_rsum (8192 floats)
__global__ __launch_bounds__(256) void prep(
    const float* __restrict__ x,
    const float* __restrict__ Wq, const float* __restrict__ Wk,
    const float* __restrict__ Wv,
    __half* __restrict__ xh,
    __half* __restrict__ wqt, __half* __restrict__ wkt, __half* __restrict__ wvt,
    float* __restrict__ rsum)
{
    const int bid = blockIdx.x;
    if (bid < 8192) {
        int i = bid * 256 + threadIdx.x;
        float4 v = reinterpret_cast<const float4*>(x)[i];
        __half2 lo = __floats2half2_rn(v.x, v.y);
        __half2 hi = __floats2half2_rn(v.z, v.w);
        reinterpret_cast<uint2*>(xh)[i] =
            make_uint2(*reinterpret_cast<uint32_t*>(&lo), *reinterpret_cast<uint32_t*>(&hi));
        return;
    }
    if (bid >= 11264) {
        int i = (bid - 11264) * 256 + threadIdx.x;   // < 2048 float4
        reinterpret_cast<float4*>(rsum)[i] = make_float4(0.f, 0.f, 0.f, 0.f);
        return;
    }
    __shared__ float t[32][33];
    const int tb = bid - 8192;                  // 0..3071
    const int w = tb >> 10;
    const int tile = tb & 1023;
    const float* in = (w == 0) ? Wq : (w == 1) ? Wk : Wv;
    __half* out = (w == 0) ? wqt : (w == 1) ? wkt : wvt;
    const int bx = tile & 31, by = tile >> 5;
    const int tx = threadIdx.x & 31, ty = threadIdx.x >> 5;
    const int xcol = bx * 32 + tx;
    const int yrow = by * 32 + ty;
#pragma unroll
    for (int j = 0; j < 32; j += 8)
        t[ty + j][tx] = in[(size_t)(yrow + j) * PP + xcol];
    __syncthreads();
    const int x2 = by * 32 + tx;
    const int y2 = bx * 32 + ty;
#pragma unroll
    for (int j = 0; j < 32; j += 8)
        out[(size_t)(y2 + j) * DD + x2] = __float2half_rn(t[tx][ty + j]);
}

// ---------------- fp16 mma.sync NT GEMM (proven mainloop) --------------------
// C[m,n] = sum_k A[m,k] * B[n,k]; A,B half row-major, leading dim in halves.
// 128x128 CTA tile, BK=32, 4 stages, 256 threads (8 warps 4x2, warp 32x64).
// MODE 0: plain, half out (projections)
// MODE 1: triangular grid (blockIdx.x packed), epilogue = exp(acc/32) masked
//         to causal region, half store + per-row-sum atomics into R
// MODE 2: K bounded at m0+128, float out scaled by 1/R[row] (context)
#define BK 32
#define TILEB 10240            // 128 rows * 80 B (40 halves padded)
#define STAGEB 20480           // A + B
#define SMEM_TOTAL 81920       // 4 stages

template <int MODE>
__global__ void __launch_bounds__(256, 2) gemm_nt_h(
    const __half* __restrict__ A, const __half* __restrict__ B, void* __restrict__ Cv,
    float* __restrict__ R,
    int lda, int ldb, int ldc, int K,
    long long sA, long long sB, long long sC)
{
    int m0, n0;
    if (MODE == 1) {
        const int tt = blockIdx.x;
        int i = (int)((sqrtf(8.0f * tt + 1.0f) - 1.0f) * 0.5f);
        while ((i + 1) * (i + 2) / 2 <= tt) i++;
        while (i * (i + 1) / 2 > tt) i--;
        const int j = tt - i * (i + 1) / 2;
        m0 = i * 128;
        n0 = j * 128;
    } else {
        m0 = blockIdx.y * 128;
        n0 = blockIdx.x * 128;
    }

    extern __shared__ char smem[];
    const int bz = blockIdx.z;
    A += (long long)bz * sA;
    B += (long long)bz * sB;

    const int tid = threadIdx.x;
    const int lane = tid & 31;
    const int wid = tid >> 5;
    const int warp_m = wid & 3;
    const int warp_n = wid >> 2;
    const int g = lane >> 2;
    const int t = lane & 3;

    const uint32_t smb = smem_u32(smem);

    int kend = K;
    if (MODE == 2) { int lim = m0 + 128; kend = (lim < K) ? lim : K; }
    const int T = kend / BK;

    float acc[2][8][4];
#pragma unroll
    for (int mt = 0; mt < 2; mt++)
#pragma unroll
        for (int nt = 0; nt < 8; nt++)
#pragma unroll
            for (int i = 0; i < 4; i++) acc[mt][nt][i] = 0.f;

    const int ldrow = tid >> 2;
    const int ldc4  = tid & 3;
    auto load_tile = [&](int kt) {
        const int k0 = kt * BK;
        const uint32_t dA = smb + (kt & 3) * STAGEB;
        const uint32_t dB = dA + TILEB;
#pragma unroll
        for (int i = 0; i < 2; i++) {
            int row = ldrow + i * 64;
            uint32_t doff = (uint32_t)(row * 80 + ldc4 * 16);
            CP_ASYNC16(dA + doff, &A[(long long)(m0 + row) * lda + k0 + ldc4 * 8]);
            CP_ASYNC16(dB + doff, &B[(long long)(n0 + row) * ldb + k0 + ldc4 * 8]);
        }
    };

#pragma unroll
    for (int p = 0; p < 3; p++) { if (p < T) load_tile(p); CP_COMMIT(); }

    const int lr = lane & 15;
    const int lcb = (lane >> 4) * 16;
    const uint32_t aRow = (uint32_t)((warp_m * 32 + lr) * 80) + lcb;
    const uint32_t bRow = (uint32_t)((warp_n * 64 + lr) * 80) + lcb;

    for (int kt = 0; kt < T; kt++) {
        CP_WAIT(2);
        __syncthreads();
        if (kt + 3 < T) load_tile(kt + 3);
        CP_COMMIT();

        const uint32_t bufA = smb + (kt & 3) * STAGEB;
        const uint32_t bufB = bufA + TILEB;

#pragma unroll
        for (int ks = 0; ks < BK; ks += 16) {
            uint32_t a[2][4];
#pragma unroll
            for (int mt = 0; mt < 2; mt++)
                LDSM_X4(a[mt][0], a[mt][1], a[mt][2], a[mt][3],
                        bufA + aRow + (uint32_t)(mt * 16 * 80 + ks * 2));
            uint32_t b[8][2];
#pragma unroll
            for (int p = 0; p < 4; p++) {
                uint32_t r0, r1, r2, r3;
                LDSM_X4(r0, r1, r2, r3,
                        bufB + bRow + (uint32_t)(p * 16 * 80 + ks * 2));
                b[2*p][0] = r0; b[2*p+1][0] = r1;
                b[2*p][1] = r2; b[2*p+1][1] = r3;
            }
#pragma unroll
            for (int mt = 0; mt < 2; mt++)
#pragma unroll
                for (int nt = 0; nt < 8; nt++)
                    mma_f16(acc[mt][nt], a[mt], b[nt]);
        }
    }

    // ---- epilogues ----
    if (MODE == 0) {
        __half* C = reinterpret_cast<__half*>(Cv) + (long long)bz * sC;
#pragma unroll
        for (int mt = 0; mt < 2; mt++) {
            long long r = m0 + warp_m * 32 + mt * 16 + g;
#pragma unroll
            for (int nt = 0; nt < 8; nt++) {
                int c = n0 + warp_n * 64 + nt * 8 + t * 2;
                *reinterpret_cast<__half2*>(&C[r * ldc + c]) =
                    __floats2half2_rn(acc[mt][nt][0], acc[mt][nt][1]);
                *reinterpret_cast<__half2*>(&C[(r + 8) * ldc + c]) =
                    __floats2half2_rn(acc[mt][nt][2], acc[mt][nt][3]);
            }
        }
    } else if (MODE == 1) {
        // E = exp(logit), causal mask, half store, per-row sums (of rounded E)
        __half* C = reinterpret_cast<__half*>(Cv) + (long long)bz * sC;
        float* RS = R + (size_t)bz * SS;
#pragma unroll
        for (int mt = 0; mt < 2; mt++) {
            const int r0i = m0 + warp_m * 32 + mt * 16 + g;
            const int r1i = r0i + 8;
            float s0 = 0.f, s1 = 0.f;
#pragma unroll
            for (int nt = 0; nt < 8; nt++) {
                int c = n0 + warp_n * 64 + nt * 8 + t * 2;
                float e0 = (c     <= r0i) ? __expf(acc[mt][nt][0] * 0.03125f) : 0.f;
                float e1 = (c + 1 <= r0i) ? __expf(acc[mt][nt][1] * 0.03125f) : 0.f;
                float e2 = (c     <= r1i) ? __expf(acc[mt][nt][2] * 0.03125f) : 0.f;
                float e3 = (c + 1 <= r1i) ? __expf(acc[mt][nt][3] * 0.03125f) : 0.f;
                __half2 h01 = __floats2half2_rn(e0, e1);
                __half2 h23 = __floats2half2_rn(e2, e3);
                *reinterpret_cast<__half2*>(&C[(long long)r0i * ldc + c]) = h01;
                *reinterpret_cast<__half2*>(&C[(long long)r1i * ldc + c]) = h23;
                float2 f01 = __half22float2(h01);
                float2 f23 = __half22float2(h23);
                s0 += f01.x + f01.y;
                s1 += f23.x + f23.y;
            }
            s0 += __shfl_xor_sync(0xffffffffu, s0, 1);
            s0 += __shfl_xor_sync(0xffffffffu, s0, 2);
            s1 += __shfl_xor_sync(0xffffffffu, s1, 1);
            s1 += __shfl_xor_sync(0xffffffffu, s1, 2);
            if (t == 0) {
                atomicAdd(&RS[r0i], s0);
                atomicAdd(&RS[r1i], s1);
            }
        }
    } else {
        // context: scale rows by 1/rowsum
        float* C = reinterpret_cast<float*>(Cv) + (long long)bz * sC;
        const float* RS = R + (size_t)bz * SS;
#pragma unroll
        for (int mt = 0; mt < 2; mt++) {
            const int r0i = m0 + warp_m * 32 + mt * 16 + g;
            const int r1i = r0i + 8;
            const float inv0 = 1.0f / RS[r0i];
            const float inv1 = 1.0f / RS[r1i];
#pragma unroll
            for (int nt = 0; nt < 8; nt++) {
                int c = n0 + warp_n * 64 + nt * 8 + t * 2;
                *reinterpret_cast<float2*>(&C[(long long)r0i * ldc + c]) =
                    make_float2(acc[mt][nt][0] * inv0, acc[mt][nt][1] * inv0);
                *reinterpret_cast<float2*>(&C[(long long)r1i * ldc + c]) =
                    make_float2(acc[mt][nt][2] * inv1, acc[mt][nt][3] * inv1);
            }
        }
    }
}

// ---------------- driver ----------------------------------------------------
extern "C" void kernel_launch(void* const* d_in, const int* in_sizes, int n_in,
                              void* d_out, int out_size)
{
    const float* x  = (const float*)d_in[0];
    const float* Wq = (const float*)d_in[1];
    const float* Wk = (const float*)d_in[2];
    const float* Wv = (const float*)d_in[3];
    float* out = (float*)d_out;

    __half *qh, *kh, *vt, *ph, *xh, *wt;
    float* rs;
    cudaGetSymbolAddress((void**)&qh, g_qh);
    cudaGetSymbolAddress((void**)&kh, g_kh);
    cudaGetSymbolAddress((void**)&vt, g_vt);
    cudaGetSymbolAddress((void**)&ph, g_ph);
    cudaGetSymbolAddress((void**)&rs, g_rsum);
    cudaGetSymbolAddress((void**)&xh, g_xh);
    cudaGetSymbolAddress((void**)&wt, g_wt);
    __half* wqt = wt;
    __half* wkt = wt + (size_t)PP * DD;
    __half* wvt = wt + (size_t)2 * PP * DD;

    cudaFuncSetAttribute(gemm_nt_h<0>, cudaFuncAttributeMaxDynamicSharedMemorySize, SMEM_TOTAL);
    cudaFuncSetAttribute(gemm_nt_h<1>, cudaFuncAttributeMaxDynamicSharedMemorySize, SMEM_TOTAL);
    cudaFuncSetAttribute(gemm_nt_h<2>, cudaFuncAttributeMaxDynamicSharedMemorySize, SMEM_TOTAL);

    // 0) fused prep: x -> half, W transposes, rsum zero (one launch)
    prep<<<8192 + 3072 + 8, 256>>>(x, Wq, Wk, Wv, xh, wqt, wkt, wvt, rs);

    const long long sSP  = (long long)SS * PP;
    const long long sSD  = (long long)SS * DD;
    const long long sPS  = (long long)PP * SS;
    const long long sSSq = (long long)SS * SS;

    // 1) q, k: NT(xh, W^T)  M=B*S, N=P, K=D
    dim3 gp(PP / 128, (BB * SS) / 128, 1);
    gemm_nt_h<0><<<gp, 256, SMEM_TOTAL>>>(xh, wqt, qh, rs, DD, DD, PP, DD, 0, 0, 0);
    gemm_nt_h<0><<<gp, 256, SMEM_TOTAL>>>(xh, wkt, kh, rs, DD, DD, PP, DD, 0, 0, 0);

    // 2) v^T per batch: NT(Wv^T, xh_b)  M=P, N=S, K=D
    dim3 gv(SS / 128, PP / 128, BB);
    gemm_nt_h<0><<<gv, 256, SMEM_TOTAL>>>(wvt, xh, vt, rs, DD, DD, SS, DD, 0, sSD, sPS);

    // 3) scores+exp: NT(q_b, k_b), triangular grid; writes E (half) + rowsums
    dim3 gs(136, 1, BB);
    gemm_nt_h<1><<<gs, 256, SMEM_TOTAL>>>(qh, kh, ph, rs, PP, PP, SS, PP, sSP, sSP, sSSq);

    // 4) context: NT(E_b, v^T_b)  M=S, N=P, K bounded at m0+128; /rowsum
    dim3 gc(PP / 128, SS / 128, BB);
    gemm_nt_h<2><<<gc, 256, SMEM_TOTAL>>>(ph, vt, out, rs, SS, SS, PP, SS, sSSq, sPS, sSP);
}